// round 12
// baseline (speedup 1.0000x reference)
#include <cuda_runtime.h>
#include <cuda_bf16.h>
#include <cstdint>

// XLSTM social pooling as dense masked GEMM via mma.sync (HMMA bf16).
//
// Per CTA (grid = 64 batches x 2 i-halves, 512 threads / 16 warps):
//   D[i(128), h(128)] = sum_{k=0..511} A[i,k] * B[k,h]
//   k<256: A = mask bits, B = bf16_hi(H);  k>=256: same mask, B = bf16_lo.
// Warp (wi 0..3, wh 0..1, ks 0..1): tile 32i x 64h, ks = hi/lo K-half.
// ks=1 warps spill accs to smem (reusing H region), ks=0 warps reduce+scale+store.

#define NA   256
#define NB   64
#define SEQL 20
#define HID  128

#define THREADS 512

#define PS_OFF   0                    // float2[256]
#define CNT_OFF  2048                 // float[128]
#define MSK_OFF  2560                 // u32[128][8]
#define H_OFF    8192                 // bf16[512][128], 256B rows, swizzled (128KB)
#define SMEM_BYTES (H_OFF + 512 * 256)

__device__ __forceinline__ uint32_t smem_u32(const void* p) {
    uint32_t a;
    asm("{ .reg .u64 t; cvta.to.shared.u64 t, %1; cvt.u32.u64 %0, t; }" : "=r"(a) : "l"(p));
    return a;
}

__device__ __forceinline__ void ldsm4t(uint32_t& r0, uint32_t& r1, uint32_t& r2,
                                       uint32_t& r3, uint32_t addr) {
    asm volatile("ldmatrix.sync.aligned.m8n8.x4.trans.shared.b16 {%0,%1,%2,%3}, [%4];"
                 : "=r"(r0), "=r"(r1), "=r"(r2), "=r"(r3) : "r"(addr));
}

__device__ __forceinline__ void mma_bf16(float* c, const uint32_t* a,
                                         uint32_t b0, uint32_t b1) {
    asm volatile(
        "mma.sync.aligned.m16n8k16.row.col.f32.bf16.bf16.f32 "
        "{%0,%1,%2,%3}, {%4,%5,%6,%7}, {%8,%9}, {%0,%1,%2,%3};"
        : "+f"(c[0]), "+f"(c[1]), "+f"(c[2]), "+f"(c[3])
        : "r"(a[0]), "r"(a[1]), "r"(a[2]), "r"(a[3]), "r"(b0), "r"(b1));
}

// 2 mask bits -> packed bf16x2 {1.0 or 0, 1.0 or 0}
__device__ __forceinline__ uint32_t bits2bf(uint32_t w, int sh) {
    const uint32_t p = (w >> sh) & 3u;
    return (p & 1u) * 0x3F80u + (p & 2u) * 0x1FC00000u;
}

__global__ __launch_bounds__(THREADS, 1)
void social_pool_hmma(const float* __restrict__ hidden,
                      const float* __restrict__ pos,
                      const float* __restrict__ radius_ptr,
                      float* __restrict__ out)
{
    extern __shared__ char smem[];
    const uint32_t sb = smem_u32(smem);
    float2*   ps   = (float2*)(smem + PS_OFF);
    float*    cnts = (float*)(smem + CNT_OFF);
    uint32_t* msk  = (uint32_t*)(smem + MSK_OFF);   // [128][8]

    const int tid  = threadIdx.x;
    const int wid  = tid >> 5;
    const int lane = tid & 31;
    const int b     = blockIdx.x >> 1;
    const int ihalf = blockIdx.x & 1;

    // --- stage positions (last timestep) ---
    if (tid < NA) {
        const float* pp = pos + ((size_t)(tid * NB + b) * SEQL + (SEQL - 1)) * 2;
        ps[tid] = make_float2(pp[0], pp[1]);
    }
    __syncthreads();

    const float r  = *radius_ptr;
    const float r2 = r * r;

    // --- mask bitmasks + counts: warp w -> i-local rows [w*8, w*8+8) ---
    {
        float2 pjr[8];
        #pragma unroll
        for (int g2 = 0; g2 < 8; g2++) pjr[g2] = ps[g2 * 32 + lane];

        #pragma unroll
        for (int k = 0; k < 8; k++) {
            const int il = wid * 8 + k;
            const int ig = ihalf * 128 + il;
            const float2 pi = ps[ig];
            int cnt = 0;
            #pragma unroll
            for (int g2 = 0; g2 < 8; g2++) {
                const int jg = g2 * 32 + lane;
                const float dx = pi.x - pjr[g2].x;
                const float dy = pi.y - pjr[g2].y;
                const bool ok = (dx * dx + dy * dy <= r2) && (jg != ig);
                const unsigned bm = __ballot_sync(0xffffffffu, ok);
                cnt += __popc(bm);
                if (lane == 0) msk[il * 8 + g2] = bm;
            }
            if (lane == 0) cnts[il] = 1.0f / fmaxf((float)cnt, 1.0f);
        }
    }

    // --- stage H hi/lo bf16, swizzled: warp w -> j rows [w*16, w*16+16) ---
    #pragma unroll
    for (int k = 0; k < 16; k++) {
        const int j = wid * 16 + k;
        const float4 v = *(const float4*)
            (hidden + ((size_t)(j * NB + b) * SEQL + (SEQL - 1)) * HID + lane * 4);

        const __nv_bfloat162 h01 = __float22bfloat162_rn(make_float2(v.x, v.y));
        const __nv_bfloat162 h23 = __float22bfloat162_rn(make_float2(v.z, v.w));
        const float2 b01 = __bfloat1622float2(h01);
        const float2 b23 = __bfloat1622float2(h23);
        const __nv_bfloat162 l01 =
            __float22bfloat162_rn(make_float2(v.x - b01.x, v.y - b01.y));
        const __nv_bfloat162 l23 =
            __float22bfloat162_rn(make_float2(v.z - b23.x, v.w - b23.y));

        const uint32_t col = ((uint32_t)(lane * 8)) ^ (((uint32_t)(j & 7)) << 4);
        uint2 hv, lv;
        hv.x = *(const uint32_t*)&h01;  hv.y = *(const uint32_t*)&h23;
        lv.x = *(const uint32_t*)&l01;  lv.y = *(const uint32_t*)&l23;
        *(uint2*)(smem + H_OFF + (size_t)j * 256 + col) = hv;
        *(uint2*)(smem + H_OFF + (size_t)(j + 256) * 256 + col) = lv;
    }
    __syncthreads();

    // --- GEMM: warp (wi, wh, ks) -> tile 32i x 64h, K-half ks ---
    const int ks = wid & 1;           // 0 = hi rows (j 0..255), 1 = lo rows
    const int wh = (wid >> 1) & 1;
    const int wi = wid >> 2;
    const int ibase = wi * 32, hbase = wh * 64;
    const int g = lane >> 2, t = lane & 3;
    const int lr = lane & 7, lmi = lane >> 3;

    float acc[2][8][4];
    #pragma unroll
    for (int mt = 0; mt < 2; mt++)
        #pragma unroll
        for (int nt = 0; nt < 8; nt++)
            #pragma unroll
            for (int c = 0; c < 4; c++) acc[mt][nt][c] = 0.0f;

    #pragma unroll
    for (int sloc = 0; sloc < 16; sloc++) {
        const int j0 = sloc * 16;
        const int jj = ks * 256 + j0 + (lmi & 1) * 8 + lr;

        uint32_t bf[4][4];
        #pragma unroll
        for (int np = 0; np < 4; np++) {
            const uint32_t colb =
                ((uint32_t)((hbase + np * 16 + (lmi >> 1) * 8) * 2)) ^
                (((uint32_t)lr) << 4);
            ldsm4t(bf[np][0], bf[np][1], bf[np][2], bf[np][3],
                   sb + H_OFF + (uint32_t)jj * 256 + colb);
        }

        const int jw = sloc >> 1;
        const int sh = ((sloc & 1) << 4) + 2 * t;
        uint32_t a[2][4];
        #pragma unroll
        for (int mt = 0; mt < 2; mt++) {
            const int r0 = ibase + mt * 16 + g;
            const uint32_t w0 = msk[r0 * 8 + jw];
            const uint32_t w1 = msk[(r0 + 8) * 8 + jw];
            a[mt][0] = bits2bf(w0, sh);
            a[mt][1] = bits2bf(w1, sh);
            a[mt][2] = bits2bf(w0, sh + 8);
            a[mt][3] = bits2bf(w1, sh + 8);
        }

        #pragma unroll
        for (int mt = 0; mt < 2; mt++)
            #pragma unroll
            for (int nt = 0; nt < 8; nt++)
                mma_bf16(acc[mt][nt], a[mt], bf[nt >> 1][(nt & 1) * 2],
                         bf[nt >> 1][(nt & 1) * 2 + 1]);
    }

    // --- cross-warp reduce (ks=1 -> smem, reusing H region) + epilogue ---
    __syncthreads();                       // all LDSM reads of H are done
    float* red = (float*)(smem + H_OFF);   // 8 tiles x 2048 floats = 64KB
    const int tileid = wid >> 1;           // (wi*2 + wh)

    if (ks == 1) {
        #pragma unroll
        for (int mt = 0; mt < 2; mt++)
            #pragma unroll
            for (int nt = 0; nt < 8; nt++)
                *(float4*)(red + tileid * 2048 + (mt * 8 + nt) * 128 + lane * 4)
                    = *(const float4*)acc[mt][nt];
    }
    __syncthreads();

    if (ks == 0) {
        #pragma unroll
        for (int mt = 0; mt < 2; mt++) {
            const int il0 = ibase + mt * 16 + g;
            const float s0 = cnts[il0];
            const float s1 = cnts[il0 + 8];
            const int ig0 = ihalf * 128 + il0;
            #pragma unroll
            for (int nt = 0; nt < 8; nt++) {
                const float4 o =
                    *(const float4*)(red + tileid * 2048 + (mt * 8 + nt) * 128 + lane * 4);
                const int h = hbase + nt * 8 + 2 * t;
                float2 v0 = make_float2((acc[mt][nt][0] + o.x) * s0,
                                        (acc[mt][nt][1] + o.y) * s0);
                float2 v1 = make_float2((acc[mt][nt][2] + o.z) * s1,
                                        (acc[mt][nt][3] + o.w) * s1);
                *(float2*)(out + ((size_t)ig0 * NB + b) * HID + h) = v0;
                *(float2*)(out + ((size_t)(ig0 + 8) * NB + b) * HID + h) = v1;
            }
        }
    }
}

extern "C" void kernel_launch(void* const* d_in, const int* in_sizes, int n_in,
                              void* d_out, int out_size)
{
    const float* hidden = (const float*)d_in[0];   // (256,64,20,128) f32
    const float* pos    = (const float*)d_in[1];   // (256,64,20,2)  f32
    const float* radius = (const float*)d_in[2];   // scalar f32
    float* out = (float*)d_out;                    // (256,64,128)   f32

    cudaFuncSetAttribute(social_pool_hmma,
                         cudaFuncAttributeMaxDynamicSharedMemorySize,
                         SMEM_BYTES);

    social_pool_hmma<<<NB * 2, THREADS, SMEM_BYTES>>>(hidden, pos, radius, out);
}

// round 13
// speedup vs baseline: 1.2581x; 1.2581x over previous
#include <cuda_runtime.h>
#include <cuda_bf16.h>
#include <cstdint>

// XLSTM social pooling as dense masked GEMM via mma.sync (HMMA bf16).
//
// Per CTA (grid = 64 batches x 2 i-halves, 512 threads / 16 warps):
//   D[i(128), h(128)] = sum_{k=0..511} A[i,k] * B[k,h]
//   k<256: A = mask bits, B = bf16_hi(H);  k>=256: same mask bits, B = bf16_lo.
// Warp (wi 0..3, wh 0..3): tile 32i x 32h, full K per warp (no K-split, no
// reduction, acc = 32 regs). A is synthesized ONCE per 16-j block and reused
// for both the hi and lo K-halves (mask identical) -> half the bits2bf ALU.

#define NA   256
#define NB   64
#define SEQL 20
#define HID  128

#define THREADS 512

#define PS_OFF   0                    // float2[256]
#define CNT_OFF  2048                 // float[128]
#define MSK_OFF  2560                 // u32[128][8]
#define H_OFF    8192                 // bf16[512][128], 256B rows, swizzled (128KB)
#define SMEM_BYTES (H_OFF + 512 * 256)

__device__ __forceinline__ uint32_t smem_u32(const void* p) {
    uint32_t a;
    asm("{ .reg .u64 t; cvta.to.shared.u64 t, %1; cvt.u32.u64 %0, t; }" : "=r"(a) : "l"(p));
    return a;
}

__device__ __forceinline__ void ldsm4t(uint32_t& r0, uint32_t& r1, uint32_t& r2,
                                       uint32_t& r3, uint32_t addr) {
    asm volatile("ldmatrix.sync.aligned.m8n8.x4.trans.shared.b16 {%0,%1,%2,%3}, [%4];"
                 : "=r"(r0), "=r"(r1), "=r"(r2), "=r"(r3) : "r"(addr));
}

__device__ __forceinline__ void mma_bf16(float* c, const uint32_t* a,
                                         uint32_t b0, uint32_t b1) {
    asm volatile(
        "mma.sync.aligned.m16n8k16.row.col.f32.bf16.bf16.f32 "
        "{%0,%1,%2,%3}, {%4,%5,%6,%7}, {%8,%9}, {%0,%1,%2,%3};"
        : "+f"(c[0]), "+f"(c[1]), "+f"(c[2]), "+f"(c[3])
        : "r"(a[0]), "r"(a[1]), "r"(a[2]), "r"(a[3]), "r"(b0), "r"(b1));
}

// 2 mask bits -> packed bf16x2 {1.0 or 0, 1.0 or 0}
__device__ __forceinline__ uint32_t bits2bf(uint32_t w, int sh) {
    const uint32_t p = (w >> sh) & 3u;
    return (p & 1u) * 0x3F80u + (p & 2u) * 0x1FC00000u;
}

__global__ __launch_bounds__(THREADS, 1)
void social_pool_hmma(const float* __restrict__ hidden,
                      const float* __restrict__ pos,
                      const float* __restrict__ radius_ptr,
                      float* __restrict__ out)
{
    extern __shared__ char smem[];
    const uint32_t sb = smem_u32(smem);
    float2*   ps   = (float2*)(smem + PS_OFF);
    float*    cnts = (float*)(smem + CNT_OFF);
    uint32_t* msk  = (uint32_t*)(smem + MSK_OFF);   // [128][8]

    const int tid  = threadIdx.x;
    const int wid  = tid >> 5;
    const int lane = tid & 31;
    const int b     = blockIdx.x >> 1;
    const int ihalf = blockIdx.x & 1;

    // --- stage positions (last timestep) ---
    if (tid < NA) {
        const float* pp = pos + ((size_t)(tid * NB + b) * SEQL + (SEQL - 1)) * 2;
        ps[tid] = make_float2(pp[0], pp[1]);
    }
    __syncthreads();

    const float r  = *radius_ptr;
    const float r2 = r * r;

    // --- mask bitmasks + counts: warp w -> i-local rows [w*8, w*8+8) ---
    {
        float2 pjr[8];
        #pragma unroll
        for (int g2 = 0; g2 < 8; g2++) pjr[g2] = ps[g2 * 32 + lane];

        #pragma unroll
        for (int k = 0; k < 8; k++) {
            const int il = wid * 8 + k;
            const int ig = ihalf * 128 + il;
            const float2 pi = ps[ig];
            int cnt = 0;
            #pragma unroll
            for (int g2 = 0; g2 < 8; g2++) {
                const int jg = g2 * 32 + lane;
                const float dx = pi.x - pjr[g2].x;
                const float dy = pi.y - pjr[g2].y;
                const bool ok = (dx * dx + dy * dy <= r2) && (jg != ig);
                const unsigned bm = __ballot_sync(0xffffffffu, ok);
                cnt += __popc(bm);
                if (lane == 0) msk[il * 8 + g2] = bm;
            }
            if (lane == 0) cnts[il] = 1.0f / fmaxf((float)cnt, 1.0f);
        }
    }

    // --- stage H hi/lo bf16, swizzled: warp w -> j rows [w*16, w*16+16) ---
    #pragma unroll
    for (int k = 0; k < 16; k++) {
        const int j = wid * 16 + k;
        const float4 v = *(const float4*)
            (hidden + ((size_t)(j * NB + b) * SEQL + (SEQL - 1)) * HID + lane * 4);

        const __nv_bfloat162 h01 = __float22bfloat162_rn(make_float2(v.x, v.y));
        const __nv_bfloat162 h23 = __float22bfloat162_rn(make_float2(v.z, v.w));
        const float2 b01 = __bfloat1622float2(h01);
        const float2 b23 = __bfloat1622float2(h23);
        const __nv_bfloat162 l01 =
            __float22bfloat162_rn(make_float2(v.x - b01.x, v.y - b01.y));
        const __nv_bfloat162 l23 =
            __float22bfloat162_rn(make_float2(v.z - b23.x, v.w - b23.y));

        const uint32_t col = ((uint32_t)(lane * 8)) ^ (((uint32_t)(j & 7)) << 4);
        uint2 hv, lv;
        hv.x = *(const uint32_t*)&h01;  hv.y = *(const uint32_t*)&h23;
        lv.x = *(const uint32_t*)&l01;  lv.y = *(const uint32_t*)&l23;
        *(uint2*)(smem + H_OFF + (size_t)j * 256 + col) = hv;
        *(uint2*)(smem + H_OFF + (size_t)(j + 256) * 256 + col) = lv;
    }
    __syncthreads();

    // --- GEMM: warp (wi 0..3, wh 0..3) -> tile 32i x 32h, full K=512 ---
    const int wh = wid & 3;
    const int wi = wid >> 2;
    const int ibase = wi * 32, hbase = wh * 32;
    const int g = lane >> 2, t = lane & 3;
    const int lr = lane & 7, lmi = lane >> 3;

    float acc[2][4][4];
    #pragma unroll
    for (int mt = 0; mt < 2; mt++)
        #pragma unroll
        for (int nt = 0; nt < 4; nt++)
            #pragma unroll
            for (int c = 0; c < 4; c++) acc[mt][nt][c] = 0.0f;

    #pragma unroll
    for (int jblk = 0; jblk < 16; jblk++) {
        // A fragments from bitmasks: once per j-block, reused for hi+lo halves
        const int jw = jblk >> 1;
        const int sh = ((jblk & 1) << 4) + 2 * t;
        uint32_t a[2][4];
        #pragma unroll
        for (int mt = 0; mt < 2; mt++) {
            const int r0 = ibase + mt * 16 + g;
            const uint32_t w0 = msk[r0 * 8 + jw];
            const uint32_t w1 = msk[(r0 + 8) * 8 + jw];
            a[mt][0] = bits2bf(w0, sh);
            a[mt][1] = bits2bf(w1, sh);
            a[mt][2] = bits2bf(w0, sh + 8);
            a[mt][3] = bits2bf(w1, sh + 8);
        }

        #pragma unroll
        for (int half = 0; half < 2; half++) {
            const int jj = half * 256 + jblk * 16 + (lmi & 1) * 8 + lr;

            uint32_t bf[2][4];
            #pragma unroll
            for (int np = 0; np < 2; np++) {
                const uint32_t colb =
                    ((uint32_t)((hbase + np * 16 + (lmi >> 1) * 8) * 2)) ^
                    (((uint32_t)lr) << 4);
                ldsm4t(bf[np][0], bf[np][1], bf[np][2], bf[np][3],
                       sb + H_OFF + (uint32_t)jj * 256 + colb);
            }

            #pragma unroll
            for (int mt = 0; mt < 2; mt++)
                #pragma unroll
                for (int nt = 0; nt < 4; nt++)
                    mma_bf16(acc[mt][nt], a[mt], bf[nt >> 1][(nt & 1) * 2],
                             bf[nt >> 1][(nt & 1) * 2 + 1]);
        }
    }

    // --- epilogue: scale by 1/count, write out ---
    #pragma unroll
    for (int mt = 0; mt < 2; mt++) {
        const int il0 = ibase + mt * 16 + g;
        const float s0 = cnts[il0];
        const float s1 = cnts[il0 + 8];
        const int ig0 = ihalf * 128 + il0;
        #pragma unroll
        for (int nt = 0; nt < 4; nt++) {
            const int h = hbase + nt * 8 + 2 * t;
            float2 v0 = make_float2(acc[mt][nt][0] * s0, acc[mt][nt][1] * s0);
            float2 v1 = make_float2(acc[mt][nt][2] * s1, acc[mt][nt][3] * s1);
            *(float2*)(out + ((size_t)ig0 * NB + b) * HID + h) = v0;
            *(float2*)(out + ((size_t)(ig0 + 8) * NB + b) * HID + h) = v1;
        }
    }
}

extern "C" void kernel_launch(void* const* d_in, const int* in_sizes, int n_in,
                              void* d_out, int out_size)
{
    const float* hidden = (const float*)d_in[0];   // (256,64,20,128) f32
    const float* pos    = (const float*)d_in[1];   // (256,64,20,2)  f32
    const float* radius = (const float*)d_in[2];   // scalar f32
    float* out = (float*)d_out;                    // (256,64,128)   f32

    cudaFuncSetAttribute(social_pool_hmma,
                         cudaFuncAttributeMaxDynamicSharedMemorySize,
                         SMEM_BYTES);

    social_pool_hmma<<<NB * 2, THREADS, SMEM_BYTES>>>(hidden, pos, radius, out);
}